// round 4
// baseline (speedup 1.0000x reference)
#include <cuda_runtime.h>
#include <math.h>

#define T_ 200
#define N_ 256
#define H_ 128
#define G_ 512   // 4*H
#define V_ 50000

#define TB 10          // time-block size (divides 200)
#define NBLK (T_/TB)   // 20 blocks
#define NB 4           // sequences per cluster
#define NCLUST (N_/NB) // 64 clusters -> 128 CTAs
#define HD 64          // h-dims owned per CTA

typedef unsigned long long ull;

// Scratch (static device globals — allocation-free per harness rules)
__device__ float g_wx[(size_t)T_ * N_ * G_];    // 104.8 MB
__device__ float g_hhist[(size_t)T_ * N_ * H_]; // 26.2 MB
__device__ float g_chist[(size_t)T_ * N_ * H_]; // 26.2 MB
__device__ float g_hmean[N_ * H_];

__device__ __forceinline__ float sigf(float x) { return 1.0f / (1.0f + expf(-x)); }

// ---- packed f32x2 helpers ----
__device__ __forceinline__ ull pk2(float x, float y) {
    ull r; asm("mov.b64 %0,{%1,%2};" : "=l"(r) : "f"(x), "f"(y)); return r;
}
__device__ __forceinline__ ull f2fma(ull a, ull b, ull c) {
    ull d; asm("fma.rn.f32x2 %0,%1,%2,%3;" : "=l"(d) : "l"(a), "l"(b), "l"(c)); return d;
}
__device__ __forceinline__ float2 up2(ull v) {
    float lo, hi; asm("mov.b64 {%0,%1},%2;" : "=f"(lo), "=f"(hi) : "l"(v));
    float2 r; r.x = lo; r.y = hi; return r;
}
__device__ __forceinline__ unsigned smem_u32(const void* p) {
    unsigned a;
    asm("{ .reg .u64 t; cvta.to.shared.u64 t, %1; cvt.u32.u64 %0, t; }" : "=r"(a) : "l"(p));
    return a;
}
__device__ __forceinline__ void st_peer64(unsigned addr, ull v, unsigned peer_rank) {
    unsigned pa;
    asm("mapa.shared::cluster.u32 %0, %1, %2;" : "=r"(pa) : "r"(addr), "r"(peer_rank));
    asm volatile("st.shared::cluster.b64 [%0], %1;" :: "r"(pa), "l"(v) : "memory");
}
#define CLUSTER_SYNC() do { \
    asm volatile("barrier.cluster.arrive.aligned;" ::: "memory"); \
    asm volatile("barrier.cluster.wait.aligned;"   ::: "memory"); \
} while (0)

// ---------------------------------------------------------------------------
// Kernel 1: Wx = emb[seq] @ W + b.  128x128 tile, 8x8 register tile, f32x2.
// grid = (4 col-tiles, 400 row-tiles), 256 threads.
// ---------------------------------------------------------------------------
__global__ void __launch_bounds__(256, 1) wx_kernel(const int* __restrict__ seq,
                                                    const float* __restrict__ emb,
                                                    const float* __restrict__ W,
                                                    const float* __restrict__ b)
{
    extern __shared__ float sm[];
    float* As = sm;                  // [128][132]
    float* Bs = As + 128 * 132;      // [128][128]
    int*   ridx = (int*)(Bs + 128 * 128);

    const int tid = threadIdx.x;
    const int bc = blockIdx.x;       // col tile (0..3), 128 cols each
    const int br = blockIdx.y;       // row tile (0..399), 128 rows each

    if (tid < 128) ridx[tid] = seq[br * 128 + tid];
    __syncthreads();

    for (int p = tid; p < 128 * 32; p += 256) {
        int r = p >> 5, kq = p & 31;
        float4 v = *(const float4*)(emb + (size_t)ridx[r] * H_ + kq * 4);
        float* dst = As + r * 132 + kq * 4;
        dst[0] = v.x; dst[1] = v.y; dst[2] = v.z; dst[3] = v.w;
    }
    for (int p = tid; p < 128 * 32; p += 256) {
        int kk = p >> 5, cq = p & 31;
        *(float4*)(Bs + kk * 128 + cq * 4) =
            *(const float4*)(W + (size_t)kk * G_ + bc * 128 + cq * 4);
    }
    __syncthreads();

    const int ty = tid >> 4, tx = tid & 15;
    const int r0 = ty * 8, c0 = tx * 8;
    ull acc[8][4];
    #pragma unroll
    for (int i = 0; i < 8; i++)
        #pragma unroll
        for (int j = 0; j < 4; j++) acc[i][j] = 0ull;

    #pragma unroll 2
    for (int k = 0; k < 128; ++k) {
        ulonglong2 b01 = *(const ulonglong2*)(Bs + k * 128 + c0);
        ulonglong2 b23 = *(const ulonglong2*)(Bs + k * 128 + c0 + 4);
        #pragma unroll
        for (int i = 0; i < 8; i++) {
            float a = As[(r0 + i) * 132 + k];
            ull ap = pk2(a, a);
            acc[i][0] = f2fma(ap, b01.x, acc[i][0]);
            acc[i][1] = f2fma(ap, b01.y, acc[i][1]);
            acc[i][2] = f2fma(ap, b23.x, acc[i][2]);
            acc[i][3] = f2fma(ap, b23.y, acc[i][3]);
        }
    }

    float4 bi0 = *(const float4*)(b + bc * 128 + c0);
    float4 bi1 = *(const float4*)(b + bc * 128 + c0 + 4);
    #pragma unroll
    for (int i = 0; i < 8; i++) {
        int row = br * 128 + r0 + i;
        float2 p0 = up2(acc[i][0]), p1 = up2(acc[i][1]);
        float2 p2 = up2(acc[i][2]), p3 = up2(acc[i][3]);
        float4 o0, o1;
        o0.x = p0.x + bi0.x; o0.y = p0.y + bi0.y; o0.z = p1.x + bi0.z; o0.w = p1.y + bi0.w;
        o1.x = p2.x + bi1.x; o1.y = p2.y + bi1.y; o1.z = p3.x + bi1.z; o1.w = p3.y + bi1.w;
        __stcs((float4*)(g_wx + (size_t)row * G_ + bc * 128 + c0), o0);
        __stcs((float4*)(g_wx + (size_t)row * G_ + bc * 128 + c0 + 4), o1);
    }
}

// ---------------------------------------------------------------------------
// Kernel 2: recurrence v4 — 2-CTA cluster, U split by gate-column halves into
// smem (zero U global traffic). Each CTA owns 64 h-dims end-to-end; per step
// only the 1KB hsum half is exchanged via DSMEM + one cluster barrier.
// ---------------------------------------------------------------------------
__global__ void __launch_bounds__(256, 1) __cluster_dims__(2, 1, 1)
rec3_kernel(const float* __restrict__ mask,
            const float* __restrict__ topo,
            const float* __restrict__ U)
{
    extern __shared__ float sm[];
    float* Us    = sm;                       // [128][256]  my U columns
    float* topoT = Us + 128 * 256;           // [4][200][12]
    float* Ph    = topoT + 4 * 200 * 12;     // [TB][4][64]
    float* Pc    = Ph + TB * NB * HD;
    float* ringh = Pc + TB * NB * HD;        // [TB][4][64]
    float* ringc = ringh + TB * NB * HD;
    float* hsumP = ringc + TB * NB * HD;     // ull[2][128][4] as floats (16B rows)
    float* csum  = hsumP + 2 * 128 * 4 * 2;  // [4][64]
    float* gl    = csum + NB * HD;           // [4][256] gates (local cols)

    const int tid  = threadIdx.x;
    const int wid  = tid >> 5;
    const int lane = tid & 31;
    const unsigned rank = blockIdx.x & 1;    // cluster CTA rank (x-major)
    const int clu = blockIdx.x >> 1;
    const int n0  = clu * NB;
    const int d0  = rank * HD;               // my global dim base

    // ---- load my half of U: cols (g*128 + d0 + dl) -> Us[i][g*64+dl] ----
    for (int p = tid; p < 128 * 64; p += 256) {   // 8192 float4 slots
        int i = p >> 6, rem = p & 63;
        int g = rem >> 4, v = rem & 15;
        float4 val = *(const float4*)(U + (size_t)i * G_ + g * 128 + d0 + v * 4);
        *(float4*)(Us + i * 256 + g * 64 + v * 4) = val;
    }
    __syncthreads();

    const int ej = tid >> 6;       // elementwise identity: seq j (0..3)
    const int ed = tid & 63;       // my local dim (0..63)
    const int sp = tid >> 7;       // GEMV: seq-pair (0..1)
    const int q  = (tid & 127) * 2;// GEMV: local col pair base (0..254)
    const unsigned hsumP_base = smem_u32(hsumP);
    float hacc = 0.0f, lsum = 0.0f;

    for (int k = 0; k < NBLK; ++k) {
        const int t0 = k * TB;
        const int plen = t0 + TB;

        // ---- topo prefix (streamed) ----
        for (int r_ = wid; r_ < TB * NB; r_ += 8) {
            int tt = r_ / NB, j = r_ % NB;
            const float* src = topo + ((size_t)(t0 + tt) * N_ + (n0 + j)) * T_;
            for (int tp = lane; tp < plen; tp += 32)
                topoT[(j * 200 + tp) * 12 + tt] = __ldcs(src + tp);
        }
        __syncthreads();

        // ---- prologue: P[tt][j][my dims] from global history (tt-pair packed) ----
        if (k == 0) {
            for (int i = tid; i < 2 * TB * NB * HD; i += 256) Ph[i] = 0.0f;
        } else {
            const int j  = wid >> 1;
            const int hc = wid & 1;
            const float* hist = hc ? g_chist : g_hhist;
            float* P = hc ? Pc : Ph;
            const int dl = lane * 2;
            ull acc[5][2];
            #pragma unroll
            for (int pr = 0; pr < 5; pr++) { acc[pr][0] = 0ull; acc[pr][1] = 0ull; }
            #pragma unroll 4
            for (int tp = 0; tp < t0; ++tp) {
                float2 hv = *(const float2*)(hist + ((size_t)tp * N_ + n0 + j) * H_ + d0 + dl);
                const float* tr = topoT + (j * 200 + tp) * 12;
                ulonglong2 wA = *(const ulonglong2*)(tr);      // tt pairs (0,1),(2,3)
                ulonglong2 wB = *(const ulonglong2*)(tr + 4);  // (4,5),(6,7)
                ull        wC = *(const ull*)(tr + 8);         // (8,9)
                ull h0 = pk2(hv.x, hv.x), h1 = pk2(hv.y, hv.y);
                acc[0][0] = f2fma(wA.x, h0, acc[0][0]); acc[0][1] = f2fma(wA.x, h1, acc[0][1]);
                acc[1][0] = f2fma(wA.y, h0, acc[1][0]); acc[1][1] = f2fma(wA.y, h1, acc[1][1]);
                acc[2][0] = f2fma(wB.x, h0, acc[2][0]); acc[2][1] = f2fma(wB.x, h1, acc[2][1]);
                acc[3][0] = f2fma(wB.y, h0, acc[3][0]); acc[3][1] = f2fma(wB.y, h1, acc[3][1]);
                acc[4][0] = f2fma(wC,   h0, acc[4][0]); acc[4][1] = f2fma(wC,   h1, acc[4][1]);
            }
            #pragma unroll
            for (int pr = 0; pr < 5; pr++) {
                float2 a0 = up2(acc[pr][0]);   // (tt=2pr, 2pr+1) for dim dl
                float2 a1 = up2(acc[pr][1]);   // for dim dl+1
                P[((2 * pr)     * NB + j) * HD + dl]     = a0.x;
                P[((2 * pr + 1) * NB + j) * HD + dl]     = a0.y;
                P[((2 * pr)     * NB + j) * HD + dl + 1] = a1.x;
                P[((2 * pr + 1) * NB + j) * HD + dl + 1] = a1.y;
            }
        }
        __syncthreads();

        // ---- sequential steps ----
        for (int tt = 0; tt < TB; ++tt) {
            const int t = t0 + tt;
            const int buf = t & 1;

            // phase A: aggregate my dims; publish hsum (h,h)-packed locally+peer
            {
                float ah = Ph[(tt * NB + ej) * HD + ed];
                float ac = Pc[(tt * NB + ej) * HD + ed];
                const float* tb2 = topoT + (ej * 200 + t0) * 12 + tt;
                for (int s = 0; s < tt; ++s) {
                    float w = tb2[s * 12];
                    ah += w * ringh[(s * NB + ej) * HD + ed];
                    ac += w * ringc[(s * NB + ej) * HD + ed];
                }
                csum[ej * HD + ed] = ac;
                ull hp = pk2(ah, ah);
                unsigned addr = hsumP_base + (unsigned)(((buf * 128 + d0 + ed) * 4 + ej) * 8);
                asm volatile("st.shared.b64 [%0], %1;" :: "r"(addr), "l"(hp) : "memory");
                st_peer64(addr, hp, rank ^ 1);
            }
            CLUSTER_SYNC();

            // phase B: gates = hsum @ U(smem) + Wx   (2 cols x 2 seqs / thread)
            {
                ull a0 = 0ull, a1 = 0ull;
                const float* hb = hsumP + (buf * 128) * 8 + sp * 4;  // + i*8
                #pragma unroll 8
                for (int i = 0; i < H_; ++i) {
                    ull u2 = *(const ull*)(Us + i * 256 + q);
                    ulonglong2 hh = *(const ulonglong2*)(hb + i * 8);
                    a0 = f2fma(u2, hh.x, a0);
                    a1 = f2fma(u2, hh.y, a1);
                }
                int g = q >> 6, dlq = q & 63;
                int gc = g * 128 + d0 + dlq;                  // global col
                const float* w0 = g_wx + ((size_t)t * N_ + n0 + 2 * sp) * G_ + gc;
                float2 x0 = __ldcs((const float2*)w0);
                float2 x1 = __ldcs((const float2*)(w0 + G_));
                float2 r0 = up2(a0), r1 = up2(a1);
                *(float2*)(gl + (2 * sp)     * 256 + q) = make_float2(r0.x + x0.x, r0.y + x0.y);
                *(float2*)(gl + (2 * sp + 1) * 256 + q) = make_float2(r1.x + x1.x, r1.y + x1.y);
            }
            __syncthreads();

            // phase C: cell for my dims
            {
                float m  = mask[t * N_ + n0 + ej];
                float ig = sigf(gl[ej * 256 + ed]);
                float fg = sigf(gl[ej * 256 + 64 + ed]);
                float og = sigf(gl[ej * 256 + 128 + ed]);
                float gg = tanhf(gl[ej * 256 + 192 + ed]);
                float c  = m * (fg * csum[ej * HD + ed] + ig * gg);
                float h  = m * (og * tanhf(c));
                ringh[(tt * NB + ej) * HD + ed] = h;
                ringc[(tt * NB + ej) * HD + ed] = c;
                g_hhist[((size_t)t * N_ + n0 + ej) * H_ + d0 + ed] = h;
                g_chist[((size_t)t * N_ + n0 + ej) * H_ + d0 + ed] = c;
                hacc += m * h;
                lsum += m;
            }
            __syncthreads();
        }
    }

    g_hmean[(n0 + ej) * H_ + d0 + ed] = hacc / lsum;
    CLUSTER_SYNC();   // no CTA exits while peer DSMEM ops may be in flight
}

// ---------------------------------------------------------------------------
// Kernel 3: out = h_mean @ W_out + b_out   (f32x2 MAC loop)
// ---------------------------------------------------------------------------
__global__ void __launch_bounds__(256) out_kernel(const float* __restrict__ Wout,
                                                  const float* __restrict__ bout,
                                                  float* __restrict__ out)
{
    extern __shared__ float sm[];
    float* As = sm;                 // [64][132]
    float* Bs = sm + 64 * 132;      // [128][64]

    const int tid = threadIdx.x;
    const int bc = blockIdx.x;
    const int br = blockIdx.y;
    const int cbase = bc * 64;

    for (int p = tid; p < 64 * 32; p += 256) {
        int r = p >> 5, kq = p & 31;
        float4 v = *(const float4*)(g_hmean + (size_t)(br * 64 + r) * H_ + kq * 4);
        float* dst = As + r * 132 + kq * 4;
        dst[0] = v.x; dst[1] = v.y; dst[2] = v.z; dst[3] = v.w;
    }
    for (int p = tid; p < 128 * 16; p += 256) {
        int k = p >> 4, cq = p & 15;
        int c = cbase + cq * 4;
        float4 v = make_float4(0.f, 0.f, 0.f, 0.f);
        if (c < V_) v = *(const float4*)(Wout + (size_t)k * V_ + c);
        *(float4*)(Bs + k * 64 + cq * 4) = v;
    }
    __syncthreads();

    const int ty = tid >> 4, tx = tid & 15;
    const int r0 = ty * 4, c0 = tx * 4;
    ull a01[4], a23[4];
    #pragma unroll
    for (int i = 0; i < 4; i++) { a01[i] = 0ull; a23[i] = 0ull; }

    #pragma unroll 8
    for (int k = 0; k < 128; ++k) {
        ull A0 = pk2(As[(r0 + 0) * 132 + k], As[(r0 + 0) * 132 + k]);
        ull A1 = pk2(As[(r0 + 1) * 132 + k], As[(r0 + 1) * 132 + k]);
        ull A2 = pk2(As[(r0 + 2) * 132 + k], As[(r0 + 2) * 132 + k]);
        ull A3 = pk2(As[(r0 + 3) * 132 + k], As[(r0 + 3) * 132 + k]);
        ulonglong2 bv = *(const ulonglong2*)(Bs + k * 64 + c0);
        a01[0] = f2fma(A0, bv.x, a01[0]); a23[0] = f2fma(A0, bv.y, a23[0]);
        a01[1] = f2fma(A1, bv.x, a01[1]); a23[1] = f2fma(A1, bv.y, a23[1]);
        a01[2] = f2fma(A2, bv.x, a01[2]); a23[2] = f2fma(A2, bv.y, a23[2]);
        a01[3] = f2fma(A3, bv.x, a01[3]); a23[3] = f2fma(A3, bv.y, a23[3]);
    }

    int c = cbase + c0;
    if (c < V_) {
        float4 bias = *(const float4*)(bout + c);
        #pragma unroll
        for (int i = 0; i < 4; i++) {
            int row = br * 64 + r0 + i;
            float2 p01 = up2(a01[i]), p23 = up2(a23[i]);
            float4 o;
            o.x = p01.x + bias.x;
            o.y = p01.y + bias.y;
            o.z = p23.x + bias.z;
            o.w = p23.y + bias.w;
            *(float4*)(out + (size_t)row * V_ + c) = o;
        }
    }
}

// ---------------------------------------------------------------------------
extern "C" void kernel_launch(void* const* d_in, const int* in_sizes, int n_in,
                              void* d_out, int out_size)
{
    const int*   seq  = (const int*)d_in[0];
    const float* mask = (const float*)d_in[1];
    const float* topo = (const float*)d_in[2];
    const float* W    = (const float*)d_in[3];
    const float* U    = (const float*)d_in[4];
    const float* b    = (const float*)d_in[5];
    const float* emb  = (const float*)d_in[6];
    const float* Wout = (const float*)d_in[7];
    const float* bout = (const float*)d_in[8];
    float* out = (float*)d_out;

    const int smem_wx  = (128 * 132 + 128 * 128) * 4 + 512;  // 134,144 B
    const int smem_out = (64 * 132 + 128 * 64) * 4;          //  66,560 B
    const int smem_rec = (128 * 256 + 4 * 200 * 12 + 4 * TB * NB * HD
                          + 2 * 128 * 4 * 2 + NB * HD + NB * 256) * 4;  // 223,744 B

    cudaFuncSetAttribute(wx_kernel,   cudaFuncAttributeMaxDynamicSharedMemorySize, smem_wx);
    cudaFuncSetAttribute(out_kernel,  cudaFuncAttributeMaxDynamicSharedMemorySize, smem_out);
    cudaFuncSetAttribute(rec3_kernel, cudaFuncAttributeMaxDynamicSharedMemorySize, smem_rec);

    wx_kernel<<<dim3(4, 400), 256, smem_wx>>>(seq, emb, W, b);
    rec3_kernel<<<2 * NCLUST, 256, smem_rec>>>(mask, topo, U);
    out_kernel<<<dim3((V_ + 63) / 64, N_ / 64), 256, smem_out>>>(Wout, bout, out);
}

// round 5
// speedup vs baseline: 1.3939x; 1.3939x over previous
#include <cuda_runtime.h>
#include <math.h>

#define T_ 200
#define N_ 256
#define H_ 128
#define G_ 512   // 4*H
#define V_ 50000

#define TB 10          // time-block size (divides 200)
#define NBLK (T_/TB)   // 20 blocks
#define NB 4           // sequences per cluster
#define NCLUST (N_/NB) // 64 clusters -> 128 CTAs
#define HD 64          // h-dims owned per CTA

typedef unsigned long long ull;

// Scratch (static device globals — allocation-free per harness rules)
__device__ float g_wx[(size_t)T_ * N_ * G_];    // 104.8 MB
__device__ float g_hhist[(size_t)T_ * N_ * H_]; // 26.2 MB
__device__ float g_chist[(size_t)T_ * N_ * H_]; // 26.2 MB
__device__ float g_hmean[N_ * H_];

__device__ __forceinline__ float sigf(float x) { return 1.0f / (1.0f + expf(-x)); }

// ---- packed f32x2 helpers ----
__device__ __forceinline__ ull pk2(float x, float y) {
    ull r; asm("mov.b64 %0,{%1,%2};" : "=l"(r) : "f"(x), "f"(y)); return r;
}
__device__ __forceinline__ ull f2fma(ull a, ull b, ull c) {
    ull d; asm("fma.rn.f32x2 %0,%1,%2,%3;" : "=l"(d) : "l"(a), "l"(b), "l"(c)); return d;
}
__device__ __forceinline__ float2 up2(ull v) {
    float lo, hi; asm("mov.b64 {%0,%1},%2;" : "=f"(lo), "=f"(hi) : "l"(v));
    float2 r; r.x = lo; r.y = hi; return r;
}
__device__ __forceinline__ unsigned smem_u32(const void* p) {
    unsigned a;
    asm("{ .reg .u64 t; cvta.to.shared.u64 t, %1; cvt.u32.u64 %0, t; }" : "=r"(a) : "l"(p));
    return a;
}
__device__ __forceinline__ void st_peer32(unsigned addr, float v, unsigned peer_rank) {
    unsigned pa;
    asm("mapa.shared::cluster.u32 %0, %1, %2;" : "=r"(pa) : "r"(addr), "r"(peer_rank));
    asm volatile("st.shared::cluster.f32 [%0], %1;" :: "r"(pa), "f"(v) : "memory");
}
#define CLUSTER_SYNC() do { \
    asm volatile("barrier.cluster.arrive.aligned;" ::: "memory"); \
    asm volatile("barrier.cluster.wait.aligned;"   ::: "memory"); \
} while (0)

// ---------------------------------------------------------------------------
// Kernel 1: Wx = emb[seq] @ W + b.  64x64 tile (R3 version — best measured).
// ---------------------------------------------------------------------------
__global__ void __launch_bounds__(256) wx_kernel(const int* __restrict__ seq,
                                                 const float* __restrict__ emb,
                                                 const float* __restrict__ W,
                                                 const float* __restrict__ b)
{
    extern __shared__ float sm[];
    float* As = sm;                 // [64][132]
    float* Bs = sm + 64 * 132;      // [128][64]
    int*   ridx = (int*)(Bs + 128 * 64);

    const int tid = threadIdx.x;
    const int bc = blockIdx.x;
    const int br = blockIdx.y;

    if (tid < 64) ridx[tid] = seq[br * 64 + tid];
    __syncthreads();

    for (int p = tid; p < 64 * 32; p += 256) {
        int r = p >> 5, kq = p & 31;
        float4 v = *(const float4*)(emb + (size_t)ridx[r] * H_ + kq * 4);
        float* dst = As + r * 132 + kq * 4;
        dst[0] = v.x; dst[1] = v.y; dst[2] = v.z; dst[3] = v.w;
    }
    for (int p = tid; p < 128 * 16; p += 256) {
        int k = p >> 4, cq = p & 15;
        *(float4*)(Bs + k * 64 + cq * 4) = *(const float4*)(W + k * G_ + bc * 64 + cq * 4);
    }
    __syncthreads();

    const int ty = tid >> 4, tx = tid & 15;
    const int r0 = ty * 4, c0 = tx * 4;
    ull a01[4], a23[4];
    #pragma unroll
    for (int i = 0; i < 4; i++) { a01[i] = 0ull; a23[i] = 0ull; }

    #pragma unroll 8
    for (int k = 0; k < 128; ++k) {
        ull A0 = pk2(As[(r0 + 0) * 132 + k], As[(r0 + 0) * 132 + k]);
        ull A1 = pk2(As[(r0 + 1) * 132 + k], As[(r0 + 1) * 132 + k]);
        ull A2 = pk2(As[(r0 + 2) * 132 + k], As[(r0 + 2) * 132 + k]);
        ull A3 = pk2(As[(r0 + 3) * 132 + k], As[(r0 + 3) * 132 + k]);
        ulonglong2 bv = *(const ulonglong2*)(Bs + k * 64 + c0);
        a01[0] = f2fma(A0, bv.x, a01[0]); a23[0] = f2fma(A0, bv.y, a23[0]);
        a01[1] = f2fma(A1, bv.x, a01[1]); a23[1] = f2fma(A1, bv.y, a23[1]);
        a01[2] = f2fma(A2, bv.x, a01[2]); a23[2] = f2fma(A2, bv.y, a23[2]);
        a01[3] = f2fma(A3, bv.x, a01[3]); a23[3] = f2fma(A3, bv.y, a23[3]);
    }

    float4 bias = *(const float4*)(b + bc * 64 + c0);
    #pragma unroll
    for (int i = 0; i < 4; i++) {
        int row = br * 64 + r0 + i;
        float2 p01 = up2(a01[i]), p23 = up2(a23[i]);
        float4 o;
        o.x = p01.x + bias.x;
        o.y = p01.y + bias.y;
        o.z = p23.x + bias.z;
        o.w = p23.y + bias.w;
        __stcs((float4*)(g_wx + (size_t)row * G_ + bc * 64 + c0), o);
    }
}

// ---------------------------------------------------------------------------
// Kernel 2: recurrence v5 — 2-CTA cluster, U columns in REGISTERS (one gate
// column per thread, 128 float regs). Phase B: broadcast LDS of hsum + f2fma,
// no smem U traffic. g_wx prefetch overlaps the cluster barrier.
// ---------------------------------------------------------------------------
__global__ void __launch_bounds__(256, 1) __cluster_dims__(2, 1, 1)
rec4_kernel(const float* __restrict__ mask,
            const float* __restrict__ topo,
            const float* __restrict__ U)
{
    extern __shared__ float sm[];
    float* topoT = sm;                       // [4][200][12] = 9600
    float* Ph    = topoT + 4 * 200 * 12;     // [TB][4][64]
    float* Pc    = Ph + TB * NB * HD;
    float* ringh = Pc + TB * NB * HD;        // [TB][4][64]
    float* ringc = ringh + TB * NB * HD;
    float* hsumP = ringc + TB * NB * HD;     // [2][128][4] floats
    float* csum  = hsumP + 2 * 128 * 4;      // [4][64]
    float* gl    = csum + NB * HD;           // [4][256] gates (local cols)

    const int tid  = threadIdx.x;
    const int wid  = tid >> 5;
    const int lane = tid & 31;
    const unsigned rank = blockIdx.x & 1;
    const int clu = blockIdx.x >> 1;
    const int n0  = clu * NB;
    const int d0  = rank * HD;               // my global dim base

    // my local gate column: lc = tid; gate g, dim dl, global col gc
    const int lc = tid;
    const int gg = lc >> 6, dl = lc & 63;
    const int gc = gg * 128 + d0 + dl;

    // ---- U column into registers (statically indexed, fully unrolled) ----
    float u[H_];
    #pragma unroll
    for (int i = 0; i < H_; ++i) u[i] = U[(size_t)i * G_ + gc];

    const int ej = tid >> 6;       // elementwise identity: seq j (0..3)
    const int ed = tid & 63;       // my local dim (0..63)
    const unsigned hsumP_base = smem_u32(hsumP);
    float hacc = 0.0f, lsum = 0.0f;

    for (int k = 0; k < NBLK; ++k) {
        const int t0 = k * TB;
        const int plen = t0 + TB;

        // ---- topo prefix (streamed) ----
        for (int r_ = wid; r_ < TB * NB; r_ += 8) {
            int tt = r_ / NB, j = r_ % NB;
            const float* src = topo + ((size_t)(t0 + tt) * N_ + (n0 + j)) * T_;
            for (int tp = lane; tp < plen; tp += 32)
                topoT[(j * 200 + tp) * 12 + tt] = __ldcs(src + tp);
        }
        __syncthreads();

        // ---- prologue: P[tt][j][my dims] from global history ----
        if (k == 0) {
            for (int i = tid; i < 2 * TB * NB * HD; i += 256) Ph[i] = 0.0f;
        } else {
            const int j  = wid >> 1;
            const int hc = wid & 1;
            const float* hist = hc ? g_chist : g_hhist;
            float* P = hc ? Pc : Ph;
            const int dl2 = lane * 2;
            ull acc[5][2];
            #pragma unroll
            for (int pr = 0; pr < 5; pr++) { acc[pr][0] = 0ull; acc[pr][1] = 0ull; }
            #pragma unroll 4
            for (int tp = 0; tp < t0; ++tp) {
                float2 hv = *(const float2*)(hist + ((size_t)tp * N_ + n0 + j) * H_ + d0 + dl2);
                const float* tr = topoT + (j * 200 + tp) * 12;
                ulonglong2 wA = *(const ulonglong2*)(tr);
                ulonglong2 wB = *(const ulonglong2*)(tr + 4);
                ull        wC = *(const ull*)(tr + 8);
                ull h0 = pk2(hv.x, hv.x), h1 = pk2(hv.y, hv.y);
                acc[0][0] = f2fma(wA.x, h0, acc[0][0]); acc[0][1] = f2fma(wA.x, h1, acc[0][1]);
                acc[1][0] = f2fma(wA.y, h0, acc[1][0]); acc[1][1] = f2fma(wA.y, h1, acc[1][1]);
                acc[2][0] = f2fma(wB.x, h0, acc[2][0]); acc[2][1] = f2fma(wB.x, h1, acc[2][1]);
                acc[3][0] = f2fma(wB.y, h0, acc[3][0]); acc[3][1] = f2fma(wB.y, h1, acc[3][1]);
                acc[4][0] = f2fma(wC,   h0, acc[4][0]); acc[4][1] = f2fma(wC,   h1, acc[4][1]);
            }
            #pragma unroll
            for (int pr = 0; pr < 5; pr++) {
                float2 a0 = up2(acc[pr][0]);
                float2 a1 = up2(acc[pr][1]);
                P[((2 * pr)     * NB + j) * HD + dl2]     = a0.x;
                P[((2 * pr + 1) * NB + j) * HD + dl2]     = a0.y;
                P[((2 * pr)     * NB + j) * HD + dl2 + 1] = a1.x;
                P[((2 * pr + 1) * NB + j) * HD + dl2 + 1] = a1.y;
            }
        }
        __syncthreads();

        // ---- sequential steps ----
        for (int tt = 0; tt < TB; ++tt) {
            const int t = t0 + tt;
            const int buf = t & 1;

            // prefetch Wx row values + mask (consumed after the barrier;
            // latency hides under phase A + cluster sync)
            const float* wbase = g_wx + ((size_t)t * N_ + n0) * G_ + gc;
            float w0 = __ldcs(wbase);
            float w1 = __ldcs(wbase + G_);
            float w2 = __ldcs(wbase + 2 * G_);
            float w3 = __ldcs(wbase + 3 * G_);
            float m  = mask[t * N_ + n0 + ej];

            // phase A: aggregate my dims; publish hsum locally + to peer
            {
                float ah = Ph[(tt * NB + ej) * HD + ed];
                float ac = Pc[(tt * NB + ej) * HD + ed];
                const float* tb2 = topoT + (ej * 200 + t0) * 12 + tt;
                for (int s = 0; s < tt; ++s) {
                    float w = tb2[s * 12];
                    ah += w * ringh[(s * NB + ej) * HD + ed];
                    ac += w * ringc[(s * NB + ej) * HD + ed];
                }
                csum[ej * HD + ed] = ac;
                unsigned addr = hsumP_base + (unsigned)(((buf * 128 + d0 + ed) * 4 + ej) * 4);
                asm volatile("st.shared.f32 [%0], %1;" :: "r"(addr), "f"(ah) : "memory");
                st_peer32(addr, ah, rank ^ 1);
            }
            CLUSTER_SYNC();   // peer hsum visible; also acts as __syncthreads

            // phase B: gates(lc) = sum_i hsum[i][:] * u[i] + Wx (u in regs;
            // hsum read as warp-uniform broadcast LDS.128)
            {
                ull a01 = 0ull, a23 = 0ull;
                const float* hb = hsumP + buf * 512;
                #pragma unroll
                for (int i = 0; i < H_; ++i) {
                    ulonglong2 hh = *(const ulonglong2*)(hb + i * 4);
                    ull uu = pk2(u[i], u[i]);
                    a01 = f2fma(uu, hh.x, a01);
                    a23 = f2fma(uu, hh.y, a23);
                }
                float2 r01 = up2(a01), r23 = up2(a23);
                gl[0 * 256 + lc] = r01.x + w0;
                gl[1 * 256 + lc] = r01.y + w1;
                gl[2 * 256 + lc] = r23.x + w2;
                gl[3 * 256 + lc] = r23.y + w3;
            }
            __syncthreads();

            // phase C: cell for my dims
            {
                float ig = sigf(gl[ej * 256 + ed]);
                float fg = sigf(gl[ej * 256 + 64 + ed]);
                float og = sigf(gl[ej * 256 + 128 + ed]);
                float gt = tanhf(gl[ej * 256 + 192 + ed]);
                float c  = m * (fg * csum[ej * HD + ed] + ig * gt);
                float h  = m * (og * tanhf(c));
                ringh[(tt * NB + ej) * HD + ed] = h;
                ringc[(tt * NB + ej) * HD + ed] = c;
                g_hhist[((size_t)t * N_ + n0 + ej) * H_ + d0 + ed] = h;
                g_chist[((size_t)t * N_ + n0 + ej) * H_ + d0 + ed] = c;
                hacc += m * h;
                lsum += m;
            }
            __syncthreads();
        }
    }

    g_hmean[(n0 + ej) * H_ + d0 + ed] = hacc / lsum;
    CLUSTER_SYNC();   // no CTA exits while peer DSMEM stores may be in flight
}

// ---------------------------------------------------------------------------
// Kernel 3: out = h_mean @ W_out + b_out   (f32x2 MAC loop)
// ---------------------------------------------------------------------------
__global__ void __launch_bounds__(256) out_kernel(const float* __restrict__ Wout,
                                                  const float* __restrict__ bout,
                                                  float* __restrict__ out)
{
    extern __shared__ float sm[];
    float* As = sm;                 // [64][132]
    float* Bs = sm + 64 * 132;      // [128][64]

    const int tid = threadIdx.x;
    const int bc = blockIdx.x;
    const int br = blockIdx.y;
    const int cbase = bc * 64;

    for (int p = tid; p < 64 * 32; p += 256) {
        int r = p >> 5, kq = p & 31;
        float4 v = *(const float4*)(g_hmean + (size_t)(br * 64 + r) * H_ + kq * 4);
        float* dst = As + r * 132 + kq * 4;
        dst[0] = v.x; dst[1] = v.y; dst[2] = v.z; dst[3] = v.w;
    }
    for (int p = tid; p < 128 * 16; p += 256) {
        int k = p >> 4, cq = p & 15;
        int c = cbase + cq * 4;
        float4 v = make_float4(0.f, 0.f, 0.f, 0.f);
        if (c < V_) v = *(const float4*)(Wout + (size_t)k * V_ + c);
        *(float4*)(Bs + k * 64 + cq * 4) = v;
    }
    __syncthreads();

    const int ty = tid >> 4, tx = tid & 15;
    const int r0 = ty * 4, c0 = tx * 4;
    ull a01[4], a23[4];
    #pragma unroll
    for (int i = 0; i < 4; i++) { a01[i] = 0ull; a23[i] = 0ull; }

    #pragma unroll 8
    for (int k = 0; k < 128; ++k) {
        ull A0 = pk2(As[(r0 + 0) * 132 + k], As[(r0 + 0) * 132 + k]);
        ull A1 = pk2(As[(r0 + 1) * 132 + k], As[(r0 + 1) * 132 + k]);
        ull A2 = pk2(As[(r0 + 2) * 132 + k], As[(r0 + 2) * 132 + k]);
        ull A3 = pk2(As[(r0 + 3) * 132 + k], As[(r0 + 3) * 132 + k]);
        ulonglong2 bv = *(const ulonglong2*)(Bs + k * 64 + c0);
        a01[0] = f2fma(A0, bv.x, a01[0]); a23[0] = f2fma(A0, bv.y, a23[0]);
        a01[1] = f2fma(A1, bv.x, a01[1]); a23[1] = f2fma(A1, bv.y, a23[1]);
        a01[2] = f2fma(A2, bv.x, a01[2]); a23[2] = f2fma(A2, bv.y, a23[2]);
        a01[3] = f2fma(A3, bv.x, a01[3]); a23[3] = f2fma(A3, bv.y, a23[3]);
    }

    int c = cbase + c0;
    if (c < V_) {
        float4 bias = *(const float4*)(bout + c);
        #pragma unroll
        for (int i = 0; i < 4; i++) {
            int row = br * 64 + r0 + i;
            float2 p01 = up2(a01[i]), p23 = up2(a23[i]);
            float4 o;
            o.x = p01.x + bias.x;
            o.y = p01.y + bias.y;
            o.z = p23.x + bias.z;
            o.w = p23.y + bias.w;
            *(float4*)(out + (size_t)row * V_ + c) = o;
        }
    }
}

// ---------------------------------------------------------------------------
extern "C" void kernel_launch(void* const* d_in, const int* in_sizes, int n_in,
                              void* d_out, int out_size)
{
    const int*   seq  = (const int*)d_in[0];
    const float* mask = (const float*)d_in[1];
    const float* topo = (const float*)d_in[2];
    const float* W    = (const float*)d_in[3];
    const float* U    = (const float*)d_in[4];
    const float* b    = (const float*)d_in[5];
    const float* emb  = (const float*)d_in[6];
    const float* Wout = (const float*)d_in[7];
    const float* bout = (const float*)d_in[8];
    float* out = (float*)d_out;

    const int smem_gemm = (64 * 132 + 128 * 64 + 64) * 4;     // 66,816 B
    const int smem_rec  = (4 * 200 * 12 + 4 * TB * NB * HD
                           + 2 * 128 * 4 + NB * HD + NB * 256) * 4;  // ~88.6 KB

    cudaFuncSetAttribute(wx_kernel,   cudaFuncAttributeMaxDynamicSharedMemorySize, smem_gemm);
    cudaFuncSetAttribute(out_kernel,  cudaFuncAttributeMaxDynamicSharedMemorySize, smem_gemm);
    cudaFuncSetAttribute(rec4_kernel, cudaFuncAttributeMaxDynamicSharedMemorySize, smem_rec);

    wx_kernel<<<dim3(G_ / 64, (T_ * N_) / 64), 256, smem_gemm>>>(seq, emb, W, b);
    rec4_kernel<<<2 * NCLUST, 256, smem_rec>>>(mask, topo, U);
    out_kernel<<<dim3((V_ + 63) / 64, N_ / 64), 256, smem_gemm>>>(Wout, bout, out);
}